// round 3
// baseline (speedup 1.0000x reference)
#include <cuda_runtime.h>
#include <cuda_bf16.h>

// Problem: pixel_shuffle(x2) + depthwise 4x4 FIR ([1,3,3,1] outer / 64), pad=2.
// x: [16,128,128,128] f32  ->  out: [16,32,257,257] f32
//
// Polyphase decomposition: output (i,j) with row pair a=i>>1, col pos w=j>>1
// uses only 2x2 original pixels across the 4 sub-channels, with coeffs {1,3}.
// Vertical pass produces v[pj](w) per row-parity; horizontal pass combines
// v(w-1), v(w), v(w+1) fetched from neighbor lanes via warp shuffle.

#define TILE_RP 16      // row-pairs per block (32 output rows)
#define SROWS   18      // TILE_RP/..: h in [a0-1, a0+16]
#define SPITCH  136     // 128 cols + pads; row byte stride 544 (16B aligned at col 4)
#define NSUB    4

__global__ __launch_bounds__(256, 4)
void upsampler_kernel(const float* __restrict__ x, float* __restrict__ out)
{
    __shared__ float S[NSUB][SROWS][SPITCH];

    const int tile = blockIdx.x;   // 0..8 row tiles (129 row-pairs total)
    const int c    = blockIdx.y;   // 0..31 output channels
    const int b    = blockIdx.z;   // 0..15 batch
    const int tid  = threadIdx.x;

    const int a0   = tile * TILE_RP;   // first row-pair of this tile
    const int h_lo = a0 - 1;           // first original row needed

    // ---- zero smem (establishes halo zeros: w=-1 at col 3, w=128 at col 132,
    //      and out-of-range rows) ----
    {
        float4* s4 = reinterpret_cast<float4*>(&S[0][0][0]);
        const int n4 = NSUB * SROWS * SPITCH / 4;   // 2448
        for (int idx = tid; idx < n4; idx += 256)
            s4[idx] = make_float4(0.f, 0.f, 0.f, 0.f);
    }
    __syncthreads();

    // ---- fill interior: 4 subch x 18 rows x 128 cols, float4 coalesced ----
    {
        const float* xbase = x + (size_t)(b * 128 + c * 4) * (128 * 128);
        for (int idx = tid; idx < NSUB * SROWS * 32; idx += 256) {
            int sc  = idx / (SROWS * 32);
            int rem = idx - sc * (SROWS * 32);
            int lr  = rem >> 5;        // local smem row
            int w4  = rem & 31;        // float4 index within row
            int h   = h_lo + lr;
            if (h >= 0 && h < 128) {
                float4 v = reinterpret_cast<const float4*>(
                    xbase + ((size_t)sc * 128 + h) * 128)[w4];
                reinterpret_cast<float4*>(&S[sc][lr][4])[w4] = v;
            }
        }
    }
    __syncthreads();

    // ---- compute ----
    const int warp = tid >> 5;
    const int lane = tid & 31;
    const float c1 = 1.0f / 64.0f;
    const float c3 = 3.0f / 64.0f;
    float* obase = out + (size_t)(b * 32 + c) * (257 * 257);

    // 16 row-pairs x 5 col-chunks (30 emitted w's per chunk) = 80 warp tasks
    for (int task = warp; task < TILE_RP * 5; task += 8) {
        int rp    = task / 5;
        int chunk = task - rp * 5;
        int a     = a0 + rp;          // global row pair -> rows 2a, 2a+1
        if (a > 128) continue;        // last tile: only a=128 valid

        int w   = chunk * 30 - 1 + lane;          // -1 .. 149
        int col = (w > 128 ? 128 : w) + 4;        // clamp into padded smem (zeros)
        int r   = a - a0;                          // smem row for h = a-1

        // vertical 2-tap (per column parity), scale 1/64 folded in
        float ve0, ve1, vo0, vo1;
        {
            float Am = S[0][r][col], A0 = S[0][r + 1][col], Ap = S[0][r + 2][col];
            float Bm = S[2][r][col], B0 = S[2][r + 1][col];
            ve0 = c1 * (Am + B0) + c3 * (A0 + Bm);
            vo0 = c1 * (Ap + Bm) + c3 * (A0 + B0);
        }
        {
            float Am = S[1][r][col], A0 = S[1][r + 1][col], Ap = S[1][r + 2][col];
            float Bm = S[3][r][col], B0 = S[3][r + 1][col];
            ve1 = c1 * (Am + B0) + c3 * (A0 + Bm);
            vo1 = c1 * (Ap + Bm) + c3 * (A0 + B0);
        }

        // neighbor v's via shuffle (lane l holds position w0-1+l)
        float ve0m = __shfl_up_sync(0xffffffffu, ve0, 1);
        float ve1m = __shfl_up_sync(0xffffffffu, ve1, 1);
        float vo0m = __shfl_up_sync(0xffffffffu, vo0, 1);
        float vo1m = __shfl_up_sync(0xffffffffu, vo1, 1);
        float ve0p = __shfl_down_sync(0xffffffffu, ve0, 1);
        float vo0p = __shfl_down_sync(0xffffffffu, vo0, 1);

        // lanes 1..30 emit outputs for w in [chunk*30, chunk*30+30)
        if (lane >= 1 && lane <= 30 && w <= 128) {
            int ie = 2 * a;
            float* rowe = obase + (size_t)ie * 257;
            rowe[2 * w] = (ve0m + ve1) + 3.0f * (ve0 + ve1m);
            if (w <= 127)
                rowe[2 * w + 1] = (ve0p + ve1m) + 3.0f * (ve0 + ve1);
            if (a <= 127) {   // odd row 2a+1 <= 255
                float* rowo = rowe + 257;
                rowo[2 * w] = (vo0m + vo1) + 3.0f * (vo0 + vo1m);
                if (w <= 127)
                    rowo[2 * w + 1] = (vo0p + vo1m) + 3.0f * (vo0 + vo1);
            }
        }
    }
}

extern "C" void kernel_launch(void* const* d_in, const int* in_sizes, int n_in,
                              void* d_out, int out_size)
{
    const float* x = (const float*)d_in[0];
    // d_in[1] is the 4x4 kernel; it is by construction outer([1,3,3,1])/64,
    // which is hardcoded via the separable polyphase coefficients above.
    float* out = (float*)d_out;
    dim3 grid(9, 32, 16);   // row tiles x channels x batch
    upsampler_kernel<<<grid, 256>>>(x, out);
}

// round 5
// speedup vs baseline: 1.0678x; 1.0678x over previous
#include <cuda_runtime.h>
#include <cuda_bf16.h>

// pixel_shuffle(x2) + depthwise 4x4 FIR ([1,3,3,1] outer / 64), pad=2.
// x: [16,128,128,128] f32 -> out: [16,32,257,257] f32
//
// Smem-free design: each warp owns a 30-wide column chunk (32 lanes incl. halo)
// and marches down 33 row-pairs with rolling registers. Per iteration: 4
// coalesced LDG.32 (2 new rows per plane pair), separable polyphase vertical
// taps in registers, neighbor exchange via warp shuffle, dense float2 stores
// with per-row packing phase chosen by address parity (257-stride rows).

__device__ __forceinline__ float ldz(const float* __restrict__ p, int h, bool colok)
{
    return (colok & ((unsigned)h < 128u)) ? __ldg(p + h * 128) : 0.0f;
}

__global__ __launch_bounds__(128, 8)
void upsampler_kernel(const float* __restrict__ x, float* __restrict__ out)
{
    const int chunk = blockIdx.x;          // 0..4   (col chunks of 30 emitted w)
    const int c     = blockIdx.y;          // 0..31  output channel
    const int b     = blockIdx.z;          // 0..15  batch
    const int warp  = threadIdx.x >> 5;    // 0..3   row-pair quarter
    const int lane  = threadIdx.x & 31;

    const int w = chunk * 30 - 1 + lane;               // -1 .. 149
    const bool colok = (unsigned)w < 128u;

    // sub-channel planes: 0=(er,ec) 1=(er,oc) 2=(or,ec) 3=(or,oc)
    const float* base = x + (size_t)(b * 128 + c * 4) * 16384;
    const float* p0 = base + w;
    const float* p1 = base + 16384 + w;
    const float* p2 = base + 32768 + w;
    const float* p3 = base + 49152 + w;

    const int bc = b * 32 + c;
    float* obase = out + (size_t)bc * 66049;           // 257*257
    const bool mis_even = (bc & 1) != 0;               // even rows misaligned?
    const bool mis_odd  = !mis_even;                   // odd rows misaligned?

    const int a0 = warp * 33;
    const int a1 = (a0 + 33 < 129) ? a0 + 33 : 129;

    const float c1 = 1.0f / 64.0f;
    const float c3 = 3.0f / 64.0f;

    // rolling registers: rA*=plane0 rows a-1,a,a+1; rB*=plane2 rows a-1,a
    float rA0 = ldz(p0, a0 - 1, colok), rA1 = ldz(p0, a0, colok), rA2 = ldz(p0, a0 + 1, colok);
    float rB0 = ldz(p2, a0 - 1, colok), rB1 = ldz(p2, a0, colok);
    float sA0 = ldz(p1, a0 - 1, colok), sA1 = ldz(p1, a0, colok), sA2 = ldz(p1, a0 + 1, colok);
    float sB0 = ldz(p3, a0 - 1, colok), sB1 = ldz(p3, a0, colok);

    const bool emit = (lane >= 1) && (lane <= 30);

    for (int a = a0; a < a1; ++a) {
        // prefetch next iteration's rows (consumed after rotation)
        float nA = ldz(p0, a + 2, colok);
        float nB = ldz(p2, a + 1, colok);
        float mA = ldz(p1, a + 2, colok);
        float mB = ldz(p3, a + 1, colok);

        // vertical 2-tap polyphase, scale 1/64 folded in
        float ve0 = c1 * (rA0 + rB1) + c3 * (rA1 + rB0);
        float vo0 = c1 * (rA2 + rB0) + c3 * (rA1 + rB1);
        float ve1 = c1 * (sA0 + sB1) + c3 * (sA1 + sB0);
        float vo1 = c1 * (sA2 + sB0) + c3 * (sA1 + sB1);

        // neighbor exchange
        float ve0m = __shfl_up_sync(0xffffffffu, ve0, 1);
        float ve1m = __shfl_up_sync(0xffffffffu, ve1, 1);
        float vo0m = __shfl_up_sync(0xffffffffu, vo0, 1);
        float vo1m = __shfl_up_sync(0xffffffffu, vo1, 1);
        float ve0p = __shfl_down_sync(0xffffffffu, ve0, 1);
        float ve1p = __shfl_down_sync(0xffffffffu, ve1, 1);
        float vo0p = __shfl_down_sync(0xffffffffu, vo0, 1);
        float vo1p = __shfl_down_sync(0xffffffffu, vo1, 1);

        float* rowe = obase + (size_t)(2 * a) * 257;

        // ---- even output row 2a (always valid, a<=128) ----
        {
            float E = (ve0m + ve1) + 3.0f * (ve0 + ve1m);          // col 2w
            if (!mis_even) {
                if (emit && w <= 127) {
                    float O = (ve0p + ve1m) + 3.0f * (ve0 + ve1);  // col 2w+1
                    *reinterpret_cast<float2*>(rowe + 2 * w) = make_float2(E, O);
                } else if (emit && w == 128) {
                    rowe[256] = E;
                }
            } else {
                if (emit && w == 0) rowe[0] = E;
                if (emit && w <= 127) {
                    float O  = (ve0p + ve1m) + 3.0f * (ve0 + ve1);       // col 2w+1
                    float En = (ve0 + ve1p) + 3.0f * (ve0p + ve1);       // col 2w+2
                    *reinterpret_cast<float2*>(rowe + 2 * w + 1) = make_float2(O, En);
                }
            }
        }

        // ---- odd output row 2a+1 (valid for a<=127) ----
        if (a <= 127) {
            float* rowo = rowe + 257;
            float E = (vo0m + vo1) + 3.0f * (vo0 + vo1m);
            if (!mis_odd) {
                if (emit && w <= 127) {
                    float O = (vo0p + vo1m) + 3.0f * (vo0 + vo1);
                    *reinterpret_cast<float2*>(rowo + 2 * w) = make_float2(E, O);
                } else if (emit && w == 128) {
                    rowo[256] = E;
                }
            } else {
                if (emit && w == 0) rowo[0] = E;
                if (emit && w <= 127) {
                    float O  = (vo0p + vo1m) + 3.0f * (vo0 + vo1);
                    float En = (vo0 + vo1p) + 3.0f * (vo0p + vo1);
                    *reinterpret_cast<float2*>(rowo + 2 * w + 1) = make_float2(O, En);
                }
            }
        }

        // rotate
        rA0 = rA1; rA1 = rA2; rA2 = nA;
        rB0 = rB1; rB1 = nB;
        sA0 = sA1; sA1 = sA2; sA2 = mA;
        sB0 = sB1; sB1 = mB;
    }
}

extern "C" void kernel_launch(void* const* d_in, const int* in_sizes, int n_in,
                              void* d_out, int out_size)
{
    const float* x = (const float*)d_in[0];
    // d_in[1] is the 4x4 kernel == outer([1,3,3,1])/64, hardcoded via the
    // separable polyphase coefficients above.
    float* out = (float*)d_out;
    dim3 grid(5, 32, 16);      // col chunks x channels x batch
    upsampler_kernel<<<grid, 128>>>(x, out);
}